// round 5
// baseline (speedup 1.0000x reference)
#include <cuda_runtime.h>

// BoundaryFocalLoss: fused boundary-dilated focal BCE loss, scalar output.
// inputs: d_in[0]=inputs f32 [B*T], d_in[1]=targets i32 [B*T] (values 0/1),
//         d_in[2]=mask f32 [B*T].  out: single f32 = sum(f_loss)/sum(mask)

#define T_LEN     200000
#define B_ROWS    128
#define GPR       25000          // groups (8 elems) per row = T_LEN/8
#define NTHR      256
#define GX        98             // ceil(GPR / NTHR) = 98 (98*256 = 25088)
#define NBLK_TOT  (GX * B_ROWS)  // 12544

__device__ double   g_partial_f[NBLK_TOT];
__device__ double   g_partial_m[NBLK_TOT];
__device__ unsigned g_done_count = 0;

__device__ __forceinline__ void elem(float x, float mm, bool pos, bool bd,
                                     float& accf, float& accm) {
    float bw   = bd ? 5.0f : 1.0f;
    float ea   = __expf(-fabsf(x));
    float opea = 1.0f + ea;
    float inv  = __frcp_rn(opea);            // sigmoid(|x|)
    float adaptive = 1.5f - inv;             // 1 - |sigmoid(x)-0.5|

    float s    = pos ? 0.975f : 0.025f;      // label-smoothed target
    float aw   = pos ? 0.25f  : 0.75f;       // alpha weight
    float bce  = fmaxf(x, 0.0f) - x * s + __logf(opea);
    float pt   = __expf(-bce);
    float om   = 1.0f - pt;

    accf += aw * om * om * bce * (bw * adaptive * mm);
    accm += mm;
}

__global__ void __launch_bounds__(NTHR)
bfl_main(const float* __restrict__ in, const int* __restrict__ tgt,
         const float* __restrict__ mask, float* __restrict__ out) {
    int g   = blockIdx.x * NTHR + threadIdx.x;   // 8-elem group index within row
    int row = blockIdx.y;

    float accf = 0.0f, accm = 0.0f;

    if (g < GPR) {
        int base = row * T_LEN + g * 8;

        int4 t0 = __ldcs((const int4*)(tgt + base));
        int4 t1 = __ldcs((const int4*)(tgt + base + 4));

        // neighbor targets: 4 before (cols c0-4..c0-1), 3 after (c0+8..c0+10)
        int4 pv, nv;
        if (g > 0)        pv = __ldcs((const int4*)(tgt + base - 4));
        else              pv = make_int4(t0.x, t0.x, t0.x, t0.x);  // clamp: no transition
        if (g < GPR - 1)  nv = __ldcs((const int4*)(tgt + base + 8));
        else              nv = make_int4(t1.w, t1.w, t1.w, t1.w);  // clamp

        // pack 15 target bits: bit j = t[c0-4+j] (targets are 0/1)
        unsigned m =
            (unsigned)pv.x        | ((unsigned)pv.y << 1)  | ((unsigned)pv.z << 2)  | ((unsigned)pv.w << 3)  |
            ((unsigned)t0.x << 4) | ((unsigned)t0.y << 5)  | ((unsigned)t0.z << 6)  | ((unsigned)t0.w << 7)  |
            ((unsigned)t1.x << 8) | ((unsigned)t1.y << 9)  | ((unsigned)t1.z << 10) | ((unsigned)t1.w << 11) |
            ((unsigned)nv.x << 12)| ((unsigned)nv.y << 13) | ((unsigned)nv.z << 14);

        unsigned tm = m ^ (m >> 1);   // bit j = transition at col c0-4+j (valid j>=1)

        float4 x0 = __ldcs((const float4*)(in + base));
        float4 x1 = __ldcs((const float4*)(in + base + 4));
        float4 m0 = __ldcs((const float4*)(mask + base));
        float4 m1 = __ldcs((const float4*)(mask + base + 4));

        // elem k: pos = m bit (k+4); boundary = any of tm bits (k+1)..(k+7)
        elem(x0.x, m0.x, (m >> 4) & 1u,  ((tm >> 1) & 0x7Fu) != 0u, accf, accm);
        elem(x0.y, m0.y, (m >> 5) & 1u,  ((tm >> 2) & 0x7Fu) != 0u, accf, accm);
        elem(x0.z, m0.z, (m >> 6) & 1u,  ((tm >> 3) & 0x7Fu) != 0u, accf, accm);
        elem(x0.w, m0.w, (m >> 7) & 1u,  ((tm >> 4) & 0x7Fu) != 0u, accf, accm);
        elem(x1.x, m1.x, (m >> 8) & 1u,  ((tm >> 5) & 0x7Fu) != 0u, accf, accm);
        elem(x1.y, m1.y, (m >> 9) & 1u,  ((tm >> 6) & 0x7Fu) != 0u, accf, accm);
        elem(x1.z, m1.z, (m >> 10) & 1u, ((tm >> 7) & 0x7Fu) != 0u, accf, accm);
        elem(x1.w, m1.w, (m >> 11) & 1u, ((tm >> 8) & 0x7Fu) != 0u, accf, accm);
    }

    // block reduction in double (deterministic)
    __shared__ double sf[NTHR];
    __shared__ double sm[NTHR];
    int tid = threadIdx.x;
    sf[tid] = (double)accf;
    sm[tid] = (double)accm;
    __syncthreads();
    #pragma unroll
    for (int s = NTHR / 2; s > 0; s >>= 1) {
        if (tid < s) { sf[tid] += sf[tid + s]; sm[tid] += sm[tid + s]; }
        __syncthreads();
    }

    int bflat = blockIdx.y * gridDim.x + blockIdx.x;
    __shared__ bool is_last;
    if (tid == 0) {
        g_partial_f[bflat] = sf[0];
        g_partial_m[bflat] = sm[0];
        __threadfence();
        unsigned prev = atomicAdd(&g_done_count, 1u);
        is_last = (prev == (unsigned)(NBLK_TOT - 1));
    }
    __syncthreads();

    if (is_last) {
        double a = 0.0, b = 0.0;
        for (int i = tid; i < NBLK_TOT; i += NTHR) {
            a += g_partial_f[i];
            b += g_partial_m[i];
        }
        sf[tid] = a;
        sm[tid] = b;
        __syncthreads();
        #pragma unroll
        for (int s = NTHR / 2; s > 0; s >>= 1) {
            if (tid < s) { sf[tid] += sf[tid + s]; sm[tid] += sm[tid + s]; }
            __syncthreads();
        }
        if (tid == 0) {
            out[0] = (sm[0] > 0.0) ? (float)(sf[0] / sm[0]) : 0.0f;
            g_done_count = 0;  // reset for next graph replay
        }
    }
}

extern "C" void kernel_launch(void* const* d_in, const int* in_sizes, int n_in,
                              void* d_out, int out_size) {
    const float* in   = (const float*)d_in[0];
    const int*   tgt  = (const int*)d_in[1];
    const float* mask = (const float*)d_in[2];
    float* out = (float*)d_out;
    (void)in_sizes; (void)n_in; (void)out_size;

    dim3 grid(GX, B_ROWS);
    bfl_main<<<grid, NTHR>>>(in, tgt, mask, out);
}

// round 6
// speedup vs baseline: 1.7459x; 1.7459x over previous
#include <cuda_runtime.h>

// BoundaryFocalLoss: fused boundary-dilated focal BCE loss, scalar output.
// inputs: d_in[0]=inputs f32 [B*T], d_in[1]=targets i32 [B*T] (values 0/1),
//         d_in[2]=mask f32 [B*T].  out: single f32 = sum(f_loss)/sum(mask)

#define T_LEN     200000
#define B_ROWS    128
#define GPR       25000          // 8-elem groups per row = T_LEN/8
#define NTHR      256
#define GX        9              // blocks per row -> 9*128 = 1152 blocks (~1 wave)
#define GSTRIDE   (GX * NTHR)    // 2304 threads per row
#define NBLK_TOT  (GX * B_ROWS)  // 1152

__device__ double   g_partial_f[NBLK_TOT];
__device__ double   g_partial_m[NBLK_TOT];
__device__ unsigned g_done_count = 0;

__device__ __forceinline__ void elem(float x, float mm, bool pos, bool bd,
                                     float& accf, float& accm) {
    float bw   = bd ? 5.0f : 1.0f;
    float ea   = __expf(-fabsf(x));
    float opea = 1.0f + ea;
    float inv  = __frcp_rn(opea);            // sigmoid(|x|)
    float adaptive = 1.5f - inv;             // 1 - |sigmoid(x)-0.5|

    float s    = pos ? 0.975f : 0.025f;      // label-smoothed target
    float aw   = pos ? 0.25f  : 0.75f;       // alpha weight
    float bce  = fmaxf(x, 0.0f) - x * s + __logf(opea);
    float pt   = __expf(-bce);
    float om   = 1.0f - pt;

    accf += aw * om * om * bce * (bw * adaptive * mm);
    accm += mm;
}

__global__ void __launch_bounds__(NTHR)
bfl_main(const float* __restrict__ in, const int* __restrict__ tgt,
         const float* __restrict__ mask, float* __restrict__ out) {
    const int row      = blockIdx.y;
    const int row_base = row * T_LEN;

    double accf_d = 0.0;   // one DADD per 8 elems
    float  accm   = 0.0f;  // mask sums are small integers: exact in float

    for (int g = blockIdx.x * NTHR + threadIdx.x; g < GPR; g += GSTRIDE) {
        int base = row_base + g * 8;

        // targets: cached loads (neighbor reads reuse L1 lines)
        int4 t0 = __ldg((const int4*)(tgt + base));
        int4 t1 = __ldg((const int4*)(tgt + base + 4));
        int4 pv, nv;
        if (g > 0)        pv = __ldg((const int4*)(tgt + base - 4));
        else              pv = make_int4(t0.x, t0.x, t0.x, t0.x);  // clamp: no transition
        if (g < GPR - 1)  nv = __ldg((const int4*)(tgt + base + 8));
        else              nv = make_int4(t1.w, t1.w, t1.w, t1.w);  // clamp

        // read-once streams
        float4 x0 = __ldcs((const float4*)(in + base));
        float4 x1 = __ldcs((const float4*)(in + base + 4));
        float4 m0 = __ldcs((const float4*)(mask + base));
        float4 m1 = __ldcs((const float4*)(mask + base + 4));

        // pack 15 target bits: bit j = t[c0-4+j]  (targets are 0/1)
        unsigned m =
            (unsigned)pv.x        | ((unsigned)pv.y << 1)  | ((unsigned)pv.z << 2)  | ((unsigned)pv.w << 3)  |
            ((unsigned)t0.x << 4) | ((unsigned)t0.y << 5)  | ((unsigned)t0.z << 6)  | ((unsigned)t0.w << 7)  |
            ((unsigned)t1.x << 8) | ((unsigned)t1.y << 9)  | ((unsigned)t1.z << 10) | ((unsigned)t1.w << 11) |
            ((unsigned)nv.x << 12)| ((unsigned)nv.y << 13) | ((unsigned)nv.z << 14);

        unsigned tm = m ^ (m >> 1);   // bit j = transition at col c0-4+j (valid j>=1)

        float gf = 0.0f;  // per-group float sum
        // elem k: pos = m bit (k+4); boundary = any of tm bits (k+1)..(k+7)
        elem(x0.x, m0.x, (m >> 4) & 1u,  ((tm >> 1) & 0x7Fu) != 0u, gf, accm);
        elem(x0.y, m0.y, (m >> 5) & 1u,  ((tm >> 2) & 0x7Fu) != 0u, gf, accm);
        elem(x0.z, m0.z, (m >> 6) & 1u,  ((tm >> 3) & 0x7Fu) != 0u, gf, accm);
        elem(x0.w, m0.w, (m >> 7) & 1u,  ((tm >> 4) & 0x7Fu) != 0u, gf, accm);
        elem(x1.x, m1.x, (m >> 8) & 1u,  ((tm >> 5) & 0x7Fu) != 0u, gf, accm);
        elem(x1.y, m1.y, (m >> 9) & 1u,  ((tm >> 6) & 0x7Fu) != 0u, gf, accm);
        elem(x1.z, m1.z, (m >> 10) & 1u, ((tm >> 7) & 0x7Fu) != 0u, gf, accm);
        elem(x1.w, m1.w, (m >> 11) & 1u, ((tm >> 8) & 0x7Fu) != 0u, gf, accm);

        accf_d += (double)gf;
    }

    // block reduction in double (deterministic)
    __shared__ double sf[NTHR];
    __shared__ double sm[NTHR];
    int tid = threadIdx.x;
    sf[tid] = accf_d;
    sm[tid] = (double)accm;
    __syncthreads();
    #pragma unroll
    for (int s = NTHR / 2; s > 0; s >>= 1) {
        if (tid < s) { sf[tid] += sf[tid + s]; sm[tid] += sm[tid + s]; }
        __syncthreads();
    }

    int bflat = blockIdx.y * gridDim.x + blockIdx.x;
    __shared__ bool is_last;
    if (tid == 0) {
        g_partial_f[bflat] = sf[0];
        g_partial_m[bflat] = sm[0];
        __threadfence();
        unsigned prev = atomicAdd(&g_done_count, 1u);
        is_last = (prev == (unsigned)(NBLK_TOT - 1));
    }
    __syncthreads();

    if (is_last) {
        __threadfence();  // acquire side: make other blocks' partials visible
        double a = 0.0, b = 0.0;
        for (int i = tid; i < NBLK_TOT; i += NTHR) {
            a += g_partial_f[i];
            b += g_partial_m[i];
        }
        sf[tid] = a;
        sm[tid] = b;
        __syncthreads();
        #pragma unroll
        for (int s = NTHR / 2; s > 0; s >>= 1) {
            if (tid < s) { sf[tid] += sf[tid + s]; sm[tid] += sm[tid + s]; }
            __syncthreads();
        }
        if (tid == 0) {
            out[0] = (sm[0] > 0.0) ? (float)(sf[0] / sm[0]) : 0.0f;
            g_done_count = 0;  // reset for next graph replay
        }
    }
}

extern "C" void kernel_launch(void* const* d_in, const int* in_sizes, int n_in,
                              void* d_out, int out_size) {
    const float* in   = (const float*)d_in[0];
    const int*   tgt  = (const int*)d_in[1];
    const float* mask = (const float*)d_in[2];
    float* out = (float*)d_out;
    (void)in_sizes; (void)n_in; (void)out_size;

    dim3 grid(GX, B_ROWS);
    bfl_main<<<grid, NTHR>>>(in, tgt, mask, out);
}

// round 7
// speedup vs baseline: 1.8982x; 1.0873x over previous
#include <cuda_runtime.h>

// BoundaryFocalLoss: fused boundary-dilated focal BCE loss, scalar output.
// inputs: d_in[0]=inputs f32 [B*T], d_in[1]=targets i32 [B*T] (values 0/1),
//         d_in[2]=mask f32 [B*T].  out: single f32 = sum(f_loss)/sum(mask)

#define T_LEN     200000
#define B_ROWS    128
#define GPR       25000          // 8-elem groups per row = T_LEN/8
#define NTHR      256
#define GX        6              // blocks per row -> 6*128 = 768 blocks (one wave @ 6/SM)
#define GSTRIDE   (GX * NTHR)    // 1536 threads per row
#define NBLK_TOT  (GX * B_ROWS)  // 768

__device__ double   g_partial_f[NBLK_TOT];
__device__ double   g_partial_m[NBLK_TOT];
__device__ unsigned g_done_count = 0;

__device__ __forceinline__ void elem(float x, float mm, bool pos, bool bd,
                                     float& accf, float& accm) {
    float bw   = bd ? 5.0f : 1.0f;
    float ea   = __expf(-fabsf(x));
    float opea = 1.0f + ea;
    float inv  = __frcp_rn(opea);            // sigmoid(|x|)
    float adaptive = 1.5f - inv;             // 1 - |sigmoid(x)-0.5|

    float s    = pos ? 0.975f : 0.025f;      // label-smoothed target
    float aw   = pos ? 0.25f  : 0.75f;       // alpha weight
    float bce  = fmaxf(x, 0.0f) - x * s + __logf(opea);
    float pt   = __expf(-bce);
    float om   = 1.0f - pt;

    accf += aw * om * om * bce * (bw * adaptive * mm);
    accm += mm;
}

__global__ void __launch_bounds__(NTHR, 6)
bfl_main(const float* __restrict__ in, const int* __restrict__ tgt,
         const float* __restrict__ mask, float* __restrict__ out) {
    const int row      = blockIdx.y;
    const int row_base = row * T_LEN;

    double accf_d = 0.0;   // one DADD per 8 elems
    float  accm   = 0.0f;  // mask sums are small integers: exact in float

    for (int g = blockIdx.x * NTHR + threadIdx.x; g < GPR; g += GSTRIDE) {
        int base = row_base + g * 8;

        // targets: cached loads (neighbor reads reuse L1 lines)
        int4 t0 = __ldg((const int4*)(tgt + base));
        int4 t1 = __ldg((const int4*)(tgt + base + 4));
        int4 pv, nv;
        if (g > 0)        pv = __ldg((const int4*)(tgt + base - 4));
        else              pv = make_int4(t0.x, t0.x, t0.x, t0.x);  // clamp: no transition
        if (g < GPR - 1)  nv = __ldg((const int4*)(tgt + base + 8));
        else              nv = make_int4(t1.w, t1.w, t1.w, t1.w);  // clamp

        // read-once streams
        float4 x0 = __ldcs((const float4*)(in + base));
        float4 x1 = __ldcs((const float4*)(in + base + 4));
        float4 m0 = __ldcs((const float4*)(mask + base));
        float4 m1 = __ldcs((const float4*)(mask + base + 4));

        // pack 15 target bits: bit j = t[c0-4+j]  (targets are 0/1)
        unsigned m =
            (unsigned)pv.x        | ((unsigned)pv.y << 1)  | ((unsigned)pv.z << 2)  | ((unsigned)pv.w << 3)  |
            ((unsigned)t0.x << 4) | ((unsigned)t0.y << 5)  | ((unsigned)t0.z << 6)  | ((unsigned)t0.w << 7)  |
            ((unsigned)t1.x << 8) | ((unsigned)t1.y << 9)  | ((unsigned)t1.z << 10) | ((unsigned)t1.w << 11) |
            ((unsigned)nv.x << 12)| ((unsigned)nv.y << 13) | ((unsigned)nv.z << 14);

        unsigned tm = m ^ (m >> 1);   // bit j = transition at col c0-4+j (valid j>=1)

        float gf = 0.0f;  // per-group float sum
        // elem k: pos = m bit (k+4); boundary = any of tm bits (k+1)..(k+7)
        elem(x0.x, m0.x, (m >> 4) & 1u,  ((tm >> 1) & 0x7Fu) != 0u, gf, accm);
        elem(x0.y, m0.y, (m >> 5) & 1u,  ((tm >> 2) & 0x7Fu) != 0u, gf, accm);
        elem(x0.z, m0.z, (m >> 6) & 1u,  ((tm >> 3) & 0x7Fu) != 0u, gf, accm);
        elem(x0.w, m0.w, (m >> 7) & 1u,  ((tm >> 4) & 0x7Fu) != 0u, gf, accm);
        elem(x1.x, m1.x, (m >> 8) & 1u,  ((tm >> 5) & 0x7Fu) != 0u, gf, accm);
        elem(x1.y, m1.y, (m >> 9) & 1u,  ((tm >> 6) & 0x7Fu) != 0u, gf, accm);
        elem(x1.z, m1.z, (m >> 10) & 1u, ((tm >> 7) & 0x7Fu) != 0u, gf, accm);
        elem(x1.w, m1.w, (m >> 11) & 1u, ((tm >> 8) & 0x7Fu) != 0u, gf, accm);

        accf_d += (double)gf;
    }

    // block reduction in double (deterministic)
    __shared__ double sf[NTHR];
    __shared__ double sm[NTHR];
    int tid = threadIdx.x;
    sf[tid] = accf_d;
    sm[tid] = (double)accm;
    __syncthreads();
    #pragma unroll
    for (int s = NTHR / 2; s > 0; s >>= 1) {
        if (tid < s) { sf[tid] += sf[tid + s]; sm[tid] += sm[tid + s]; }
        __syncthreads();
    }

    int bflat = blockIdx.y * gridDim.x + blockIdx.x;
    __shared__ bool is_last;
    if (tid == 0) {
        g_partial_f[bflat] = sf[0];
        g_partial_m[bflat] = sm[0];
        __threadfence();
        unsigned prev = atomicAdd(&g_done_count, 1u);
        is_last = (prev == (unsigned)(NBLK_TOT - 1));
    }
    __syncthreads();

    if (is_last) {
        __threadfence();  // acquire side: make other blocks' partials visible
        double a = 0.0, b = 0.0;
        for (int i = tid; i < NBLK_TOT; i += NTHR) {
            a += g_partial_f[i];
            b += g_partial_m[i];
        }
        sf[tid] = a;
        sm[tid] = b;
        __syncthreads();
        #pragma unroll
        for (int s = NTHR / 2; s > 0; s >>= 1) {
            if (tid < s) { sf[tid] += sf[tid + s]; sm[tid] += sm[tid + s]; }
            __syncthreads();
        }
        if (tid == 0) {
            out[0] = (sm[0] > 0.0) ? (float)(sf[0] / sm[0]) : 0.0f;
            g_done_count = 0;  // reset for next graph replay
        }
    }
}

extern "C" void kernel_launch(void* const* d_in, const int* in_sizes, int n_in,
                              void* d_out, int out_size) {
    const float* in   = (const float*)d_in[0];
    const int*   tgt  = (const int*)d_in[1];
    const float* mask = (const float*)d_in[2];
    float* out = (float*)d_out;
    (void)in_sizes; (void)n_in; (void)out_size;

    dim3 grid(GX, B_ROWS);
    bfl_main<<<grid, NTHR>>>(in, tgt, mask, out);
}